// round 1
// baseline (speedup 1.0000x reference)
#include <cuda_runtime.h>
#include <math.h>

// Problem constants
#define BQ 32
#define DAQ 2
#define WQ 64
#define MQ 16
#define LQ 8192
#define NBQ 32          // 2*MODES (interleaved cos/sin columns)
#define KSPL 8          // K-split for forward DFT

// Scratch (device globals: allocation-free rule)
__device__ float g_hA[BQ * WQ * LQ];            // 64 MB
__device__ float g_hB[BQ * WQ * LQ];            // 64 MB
__device__ float g_T[LQ * NBQ];                 // basis table: [l][2k]=cos, [2k+1]=sin  (1 MB)
__device__ float g_Fpart[BQ * KSPL * WQ * NBQ]; // forward DFT partials (2 MB)
__device__ float g_coef[BQ * WQ * NBQ];         // inverse-DFT coefficients (1 MB)

__device__ __forceinline__ float gelu_exact(float v) {
    return 0.5f * v * (1.0f + erff(v * 0.70710678118654752440f));
}

// ---------------------------------------------------------------------------
// Basis table: T[l*32 + 2k] = cos(2*pi*k*l/L), T[l*32 + 2k+1] = sin(2*pi*k*l/L)
// Integer range reduction keeps the sincos argument in [0, 2*pi).
// ---------------------------------------------------------------------------
__global__ void build_table_kernel() {
    int idx = blockIdx.x * blockDim.x + threadIdx.x;  // 131072 = 8192*16
    int l = idx >> 4;
    int k = idx & 15;
    int m = (k * l) & (LQ - 1);
    float ang = (float)m * (6.283185307179586476925f / (float)LQ);
    float s, c;
    sincosf(ang, &s, &c);
    g_T[l * NBQ + 2 * k]     = c;
    g_T[l * NBQ + 2 * k + 1] = s;
}

// ---------------------------------------------------------------------------
// Lifting: h[b,w,l] = Pw[w,0]*x[b,0,l] + Pw[w,1]*x[b,1,l] + Pb[w]
// ---------------------------------------------------------------------------
__global__ void lift_kernel(const float* __restrict__ x,
                            const float* __restrict__ Pw,
                            const float* __restrict__ Pb,
                            float* __restrict__ h) {
    int idx = blockIdx.x * 256 + threadIdx.x;   // over B*W*L
    int l = idx & (LQ - 1);
    int w = (idx >> 13) & 63;
    int b = idx >> 19;
    float x0 = x[(b * 2 + 0) * LQ + l];
    float x1 = x[(b * 2 + 1) * LQ + l];
    h[idx] = Pw[2 * w] * x0 + Pw[2 * w + 1] * x1 + Pb[w];
}

// ---------------------------------------------------------------------------
// Forward DFT (first 16 modes) as a tiled GEMM:
//   Fpart[b, ks, c, n] = sum over l-chunk of h[b,c,l] * T[l,n]
// Grid (B, KSPL); 256 threads. smem: Ht[64][129] + Tt[128][32] = 49408 B.
// Each thread: 2 c-rows x 4 n-cols = 8 accumulators.
// ---------------------------------------------------------------------------
__global__ void __launch_bounds__(256) fwd_dft_kernel(const float* __restrict__ h) {
    extern __shared__ float sm[];
    float* Ht = sm;                // 64 * 129
    float* Tt = sm + 64 * 129;     // 128 * 32
    int b = blockIdx.x;
    int ks = blockIdx.y;
    int t = threadIdx.x;
    int cc = t & 31;
    int nq = (t >> 5) << 2;        // 0,4,...,28
    float acc0 = 0.f, acc1 = 0.f, acc2 = 0.f, acc3 = 0.f;
    float acc4 = 0.f, acc5 = 0.f, acc6 = 0.f, acc7 = 0.f;
    const int lbase = ks * (LQ / KSPL);  // 1024

    for (int ch = 0; ch < 8; ch++) {
        int l0 = lbase + ch * 128;
        __syncthreads();
#pragma unroll
        for (int j = 0; j < 32; j++) {
            int idx = t + 256 * j;       // 8192 floats
            int c = idx >> 7, l = idx & 127;
            Ht[c * 129 + l] = h[(b * 64 + c) * LQ + l0 + l];
        }
#pragma unroll
        for (int j = 0; j < 4; j++) {
            int idx = t + 256 * j;       // 1024 float4 = 128x32 floats
            ((float4*)Tt)[idx] = ((const float4*)g_T)[l0 * 8 + idx];
        }
        __syncthreads();
#pragma unroll 4
        for (int l = 0; l < 128; l++) {
            float a0 = Ht[cc * 129 + l];
            float a1 = Ht[(cc + 32) * 129 + l];
            float4 bv = *(float4*)(Tt + l * 32 + nq);  // broadcast within warp
            acc0 += a0 * bv.x; acc1 += a0 * bv.y; acc2 += a0 * bv.z; acc3 += a0 * bv.w;
            acc4 += a1 * bv.x; acc5 += a1 * bv.y; acc6 += a1 * bv.z; acc7 += a1 * bv.w;
        }
    }
    int base0 = ((b * KSPL + ks) * 64 + cc) * NBQ + nq;
    int base1 = ((b * KSPL + ks) * 64 + cc + 32) * NBQ + nq;
    *(float4*)(g_Fpart + base0) = make_float4(acc0, acc1, acc2, acc3);
    *(float4*)(g_Fpart + base1) = make_float4(acc4, acc5, acc6, acc7);
}

// ---------------------------------------------------------------------------
// Mode mixing + irfft coefficient prep.
//   Hf[b,i,k] = (S_c, -S_s)  (rfft sign convention)
//   A[b,o,k]  = sum_i (wr + i wi)[k,o,i] * Hf[b,i,k]
//   coef[b,o,2k]   = (k==0 ? 1 : 2)/L * Ar
//   coef[b,o,2k+1] = (k==0 ? 0 : -2/L * Ai)
// so x1[b,o,l] = sum_n coef[b,o,n] * T[l,n]   (irfft ignores Im of DC bin)
// Grid 512 = (b,k); 64 threads = o.
// ---------------------------------------------------------------------------
__global__ void mode_mix_kernel(const float* __restrict__ kwr,
                                const float* __restrict__ kwi, int ib) {
    int b = blockIdx.x >> 4;
    int k = blockIdx.x & 15;
    int o = threadIdx.x;
    __shared__ float Hr[64], Hs[64];
    float hr = 0.f, hs = 0.f;
#pragma unroll
    for (int p = 0; p < KSPL; p++) {
        hr += g_Fpart[((b * KSPL + p) * 64 + o) * NBQ + 2 * k];
        hs += g_Fpart[((b * KSPL + p) * 64 + o) * NBQ + 2 * k + 1];
    }
    Hr[o] = hr;
    Hs[o] = hs;
    __syncthreads();
    const float* wr = kwr + (((size_t)ib * 16 + k) * 64 + o) * 64;
    const float* wi = kwi + (((size_t)ib * 16 + k) * 64 + o) * 64;
    float ar = 0.f, ai = 0.f;
#pragma unroll 8
    for (int i = 0; i < 64; i++) {
        float xr = Hr[i];
        float xi = -Hs[i];
        float wrv = wr[i], wiv = wi[i];
        ar += wrv * xr - wiv * xi;
        ai += wrv * xi + wiv * xr;
    }
    const float invL = 1.0f / (float)LQ;
    float cC, cS;
    if (k == 0) { cC = ar * invL;        cS = 0.f; }
    else        { cC = 2.f * ar * invL;  cS = -2.f * ai * invL; }
    g_coef[(b * 64 + o) * NBQ + 2 * k]     = cC;
    g_coef[(b * 64 + o) * NBQ + 2 * k + 1] = cS;
}

// ---------------------------------------------------------------------------
// Fused inverse-DFT + 1x1 conv + bias + exact GELU.
// Grid (L/128, B); 256 threads. Thread (og = t>>7, lx = t&127) computes all
// 32 output channels o = og*32 .. og*32+31 for its l = l0+lx.
// hcol[64] and Tl[32] live in registers; weights broadcast from smem (LDS.128).
// ---------------------------------------------------------------------------
__global__ void __launch_bounds__(256) fused_block_kernel(
    const float* __restrict__ hin, float* __restrict__ hout,
    const float* __restrict__ cw, const float* __restrict__ cb, int ib) {
    __shared__ __align__(16) float coefS[NBQ * 64];   // [n][o]
    __shared__ __align__(16) float convS[64 * 64];    // [c][o]
    __shared__ __align__(16) float cbs[64];
    int b = blockIdx.y;
    int l0 = blockIdx.x * 128;
    int t = threadIdx.x;

#pragma unroll
    for (int j = 0; j < 8; j++) {
        int idx = t + 256 * j;          // 2048
        int o = idx >> 5, n = idx & 31;
        coefS[n * 64 + o] = g_coef[(b * 64 + o) * NBQ + n];
    }
#pragma unroll
    for (int j = 0; j < 16; j++) {
        int idx = t + 256 * j;          // 4096
        int o = idx >> 6, c = idx & 63;
        convS[c * 64 + o] = cw[((size_t)ib * 64 + o) * 64 + c];
    }
    if (t < 64) cbs[t] = cb[ib * 64 + t];
    __syncthreads();

    int lx = t & 127;
    int og = t >> 7;
    int l = l0 + lx;

    float hcol[64];
#pragma unroll
    for (int c = 0; c < 64; c++)
        hcol[c] = hin[(b * 64 + c) * LQ + l];

    float Tl[32];
    const float4* Trow = (const float4*)(g_T + (size_t)l * NBQ);
#pragma unroll
    for (int j = 0; j < 8; j++) {
        float4 v = Trow[j];
        Tl[4 * j] = v.x; Tl[4 * j + 1] = v.y; Tl[4 * j + 2] = v.z; Tl[4 * j + 3] = v.w;
    }

    for (int oq = 0; oq < 8; oq++) {
        int o0 = og * 32 + oq * 4;
        float4 bv = *(float4*)&cbs[o0];
        float s0 = bv.x, s1 = bv.y, s2 = bv.z, s3 = bv.w;
#pragma unroll
        for (int n = 0; n < 32; n++) {
            float4 cf = *(float4*)&coefS[n * 64 + o0];   // broadcast LDS.128
            float tv = Tl[n];
            s0 += cf.x * tv; s1 += cf.y * tv; s2 += cf.z * tv; s3 += cf.w * tv;
        }
#pragma unroll
        for (int c = 0; c < 64; c++) {
            float4 wv = *(float4*)&convS[c * 64 + o0];   // broadcast LDS.128
            float hv = hcol[c];
            s0 += wv.x * hv; s1 += wv.y * hv; s2 += wv.z * hv; s3 += wv.w * hv;
        }
        hout[(b * 64 + o0 + 0) * LQ + l] = gelu_exact(s0);
        hout[(b * 64 + o0 + 1) * LQ + l] = gelu_exact(s1);
        hout[(b * 64 + o0 + 2) * LQ + l] = gelu_exact(s2);
        hout[(b * 64 + o0 + 3) * LQ + l] = gelu_exact(s3);
    }
}

// ---------------------------------------------------------------------------
// Projection: out[b,0,l] = sum_c Qw[c]*h[b,c,l] + Qb
// ---------------------------------------------------------------------------
__global__ void proj_kernel(const float* __restrict__ h,
                            const float* __restrict__ Qw,
                            const float* __restrict__ Qb,
                            float* __restrict__ out) {
    int b = blockIdx.y;
    int l = blockIdx.x * 256 + threadIdx.x;
    float acc = Qb[0];
#pragma unroll
    for (int c = 0; c < 64; c++)
        acc += Qw[c] * h[(b * 64 + c) * LQ + l];
    out[b * LQ + l] = acc;
}

// ---------------------------------------------------------------------------
extern "C" void kernel_launch(void* const* d_in, const int* in_sizes, int n_in,
                              void* d_out, int out_size) {
    const float* x   = (const float*)d_in[0];
    const float* Pw  = (const float*)d_in[1];
    const float* Pb  = (const float*)d_in[2];
    const float* kwr = (const float*)d_in[3];
    const float* kwi = (const float*)d_in[4];
    const float* cw  = (const float*)d_in[5];
    const float* cb  = (const float*)d_in[6];
    const float* Qw  = (const float*)d_in[7];
    const float* Qb  = (const float*)d_in[8];
    float* out = (float*)d_out;

    float *hA = nullptr, *hB = nullptr;
    cudaGetSymbolAddress((void**)&hA, g_hA);
    cudaGetSymbolAddress((void**)&hB, g_hB);

    const int FWD_SMEM = (64 * 129 + 128 * 32) * 4;   // 49408 B
    cudaFuncSetAttribute(fwd_dft_kernel,
                         cudaFuncAttributeMaxDynamicSharedMemorySize, FWD_SMEM);

    build_table_kernel<<<(LQ * MQ) / 256, 256>>>();
    lift_kernel<<<(BQ * WQ * LQ) / 256, 256>>>(x, Pw, Pb, hA);

    float* cur = hA;
    float* nxt = hB;
    for (int ib = 0; ib < 4; ib++) {
        fwd_dft_kernel<<<dim3(BQ, KSPL), 256, FWD_SMEM>>>(cur);
        mode_mix_kernel<<<BQ * MQ, 64>>>(kwr, kwi, ib);
        fused_block_kernel<<<dim3(LQ / 128, BQ), 256>>>(cur, nxt, cw, cb, ib);
        float* tmp = cur; cur = nxt; nxt = tmp;
    }
    proj_kernel<<<dim3(LQ / 256, BQ), 256>>>(cur, Qw, Qb, out);
}